// round 8
// baseline (speedup 1.0000x reference)
#include <cuda_runtime.h>

#define NROWS 500000
#define DIM 256
#define GSZ 32
#define NPHASES ((NROWS + GSZ - 1) / GSZ)   // 15625 phases of 32 rows

static __device__ __forceinline__ unsigned long long pack2(float a, float b){
  unsigned long long r; asm("mov.b64 %0,{%1,%2};":"=l"(r):"f"(a),"f"(b)); return r; }
static __device__ __forceinline__ void unpack2(unsigned long long v, float&a, float&b){
  asm("mov.b64 {%0,%1},%2;":"=f"(a),"=f"(b):"l"(v)); }
static __device__ __forceinline__ unsigned long long fma2(unsigned long long a, unsigned long long b, unsigned long long c){
  unsigned long long d; asm("fma.rn.f32x2 %0,%1,%2,%3;":"=l"(d):"l"(a),"l"(b),"l"(c)); return d; }
static __device__ __forceinline__ unsigned long long add2(unsigned long long a, unsigned long long b){
  unsigned long long d; asm("add.rn.f32x2 %0,%1,%2;":"=l"(d):"l"(a),"l"(b)); return d; }
static __device__ __forceinline__ float ex2f(float a){ float r; asm("ex2.approx.f32 %0,%1;":"=f"(r):"f"(a)); return r; }
static __device__ __forceinline__ float rcpf(float a){ float r; asm("rcp.approx.f32 %0,%1;":"=f"(r):"f"(a)); return r; }

// 256-thread CTA = 2 streams x 4 warps {g1a,g1b,g2a,g2b}.
// Roles are PERMUTED between the two streams so every SMSP (wid%4) hosts a
// mix of gemm1 (shfl-chain-bound) and gemm2 (fma/mufu-bound) warps.
//   g1 half h: computes h[8h:8h+8] = relu(x @ W1[:,8h:8h+8])   (64 weight regs)
//   g2 half h: out cols [128h,128h+128) = x*sigmoid(2*(h @ W2)) (64 weight regs)
__global__ __launch_bounds__(256, 2) void fb_kernel(
    const float* __restrict__ x, const float* __restrict__ W1,
    const float* __restrict__ W2, float* __restrict__ out)
{
  __shared__ float hbuf[2][2][GSZ][16];   // [stream][buf][row][h]
  const int warp = threadIdx.x >> 5;
  const int lane = threadIdx.x & 31;
  const int s    = warp >> 2;         // stream within CTA (0,1)
  const int u    = warp & 3;          // warp within stream
  const int isg1 = (((u >> 1) ^ s) == 0);  // stream1 swaps role slots
  const int half = u & 1;
  const int vb = (int)blockIdx.x * 2 + s;
  const int nstreams = (int)gridDim.x * 2;

  int myPhases = 0;
  if (vb < NPHASES) myPhases = (NPHASES - 1 - vb) / nstreams + 1;

  if (isg1) {
    // W1 slice: input cols [lane*8,+8), outputs [half*8, half*8+8) as 4 packed pairs.
    const int jbase = half * 8;
    unsigned long long w1p[8][4];
    {
      const unsigned long long* w1u = (const unsigned long long*)W1;
      #pragma unroll
      for (int i = 0; i < 8; i++)
        #pragma unroll
        for (int p = 0; p < 4; p++)
          w1p[i][p] = __ldg(&w1u[(lane*8 + i)*8 + half*4 + p]);
    }
    for (int it = 0; it <= myPhases; it++) {
      if (it < myPhases) {
        int phase = vb + it * nstreams;
        int base = phase * GSZ;
        int rows = min(GSZ, NROWS - base);
        float* hb = &hbuf[s][it & 1][0][0];
        #pragma unroll 1
        for (int r = 0; r < rows; r++) {
          if (half == 0) {
            int pr = base + r + 4; if (pr >= NROWS) pr = NROWS - 1;
            asm volatile("prefetch.global.L2 [%0];" :: "l"(x + (size_t)pr * DIM + lane*8));
          }
          const float4* xr = (const float4*)(x + (size_t)(base + r) * DIM) + lane*2;
          float4 a = __ldg(xr), b = __ldg(xr+1);
          float xs[8] = {a.x,a.y,a.z,a.w, b.x,b.y,b.z,b.w};
          unsigned long long acc[4];
          #pragma unroll
          for (int p=0;p<4;p++) acc[p] = 0ull;
          #pragma unroll
          for (int i=0;i<8;i++) {
            unsigned long long xi = pack2(xs[i], xs[i]);
            #pragma unroll
            for (int p=0;p<4;p++) acc[p] = fma2(xi, w1p[i][p], acc[p]);
          }
          // reduce-scatter 4 pairs over 32 lanes: 2 folds + 3 adds = 6 ull shfl
          bool s16 = (lane & 16) != 0;
          bool s8  = (lane & 8)  != 0;
          unsigned long long ka = s16 ? acc[2] : acc[0];
          unsigned long long kb = s16 ? acc[3] : acc[1];
          unsigned long long sa = s16 ? acc[0] : acc[2];
          unsigned long long sb = s16 ? acc[1] : acc[3];
          ka = add2(ka, __shfl_xor_sync(0xffffffffu, sa, 16));
          kb = add2(kb, __shfl_xor_sync(0xffffffffu, sb, 16));
          unsigned long long k  = s8 ? kb : ka;
          unsigned long long sd = s8 ? ka : kb;
          k = add2(k, __shfl_xor_sync(0xffffffffu, sd, 8));
          k = add2(k, __shfl_xor_sync(0xffffffffu, k, 4));
          k = add2(k, __shfl_xor_sync(0xffffffffu, k, 2));
          k = add2(k, __shfl_xor_sync(0xffffffffu, k, 1));
          float h0, h1; unpack2(k, h0, h1);
          h0 = fmaxf(h0, 0.f); h1 = fmaxf(h1, 0.f);
          if ((lane & 7) == 0) {
            int q = ((lane>>4)&1)*2 + ((lane>>3)&1);   // pair owned by this lane
            *(float2*)(hb + r*16 + jbase + 2*q) = make_float2(h0, h1);
          }
        }
      }
      asm volatile("bar.sync %0, 128;" :: "r"(1 + s) : "memory");
    }
  } else {
    // W2 slice: output cols [half*128 + lane*4, +4), all 16 inputs,
    // pre-scaled by -2*log2(e): sigmoid(2m) = rcp(1 + ex2(-2m*log2e)).
    const int cb = half * 128 + lane * 4;
    unsigned long long w2p[16][2];
    {
      const float c = -2.0f * 1.4426950408889634f;
      #pragma unroll
      for (int j = 0; j < 16; j++)
        #pragma unroll
        for (int p = 0; p < 2; p++) {
          float a = __ldg(&W2[j*DIM + cb + 2*p])     * c;
          float b = __ldg(&W2[j*DIM + cb + 2*p + 1]) * c;
          w2p[j][p] = pack2(a, b);
        }
    }
    for (int it = 0; it <= myPhases; it++) {
      if (it >= 1) {
        int phase = vb + (it-1) * nstreams;
        int base = phase * GSZ;
        int rows = min(GSZ, NROWS - base);
        const float* hb = &hbuf[s][(it-1) & 1][0][0];
        #pragma unroll 1
        for (int r = 0; r < rows; r++) {
          unsigned long long acc[2];
          acc[0] = 0ull; acc[1] = 0ull;
          #pragma unroll
          for (int jj = 0; jj < 4; jj++) {
            float4 h4 = *(const float4*)(hb + r*16 + jj*4);  // broadcast LDS
            float hv[4] = {h4.x, h4.y, h4.z, h4.w};
            #pragma unroll
            for (int q = 0; q < 4; q++) {
              unsigned long long hj = pack2(hv[q], hv[q]);
              acc[0] = fma2(hj, w2p[jj*4+q][0], acc[0]);
              acc[1] = fma2(hj, w2p[jj*4+q][1], acc[1]);
            }
          }
          float4 xa = __ldg((const float4*)(x + (size_t)(base + r) * DIM + cb));
          float t0,t1,t2,t3;
          unpack2(acc[0], t0, t1);
          unpack2(acc[1], t2, t3);
          float s0 = rcpf(1.0f + ex2f(t0));
          float s1 = rcpf(1.0f + ex2f(t1));
          float s2 = rcpf(1.0f + ex2f(t2));
          float s3 = rcpf(1.0f + ex2f(t3));
          float4 o = make_float4(xa.x*s0, xa.y*s1, xa.z*s2, xa.w*s3);
          *(float4*)(out + (size_t)(base + r) * DIM + cb) = o;
        }
      }
      asm volatile("bar.sync %0, 128;" :: "r"(1 + s) : "memory");
    }
  }
}

extern "C" void kernel_launch(void* const* d_in, const int* in_sizes, int n_in,
                              void* d_out, int out_size) {
  const float* x  = (const float*)d_in[0];
  const float* W1 = (const float*)d_in[1];
  const float* W2 = (const float*)d_in[2];
  float* out = (float*)d_out;
  fb_kernel<<<296, 256>>>(x, W1, W2, out);
}

// round 12
// speedup vs baseline: 1.0133x; 1.0133x over previous
#include <cuda_runtime.h>

#define NROWS 500000
#define DIM 256
#define GSZ 32
#define NPHASES ((NROWS + GSZ - 1) / GSZ)   // 15625 phases of 32 rows

static __device__ __forceinline__ unsigned long long pack2(float a, float b){
  unsigned long long r; asm("mov.b64 %0,{%1,%2};":"=l"(r):"f"(a),"f"(b)); return r; }
static __device__ __forceinline__ void unpack2(unsigned long long v, float&a, float&b){
  asm("mov.b64 {%0,%1},%2;":"=f"(a),"=f"(b):"l"(v)); }
static __device__ __forceinline__ unsigned long long fma2(unsigned long long a, unsigned long long b, unsigned long long c){
  unsigned long long d; asm("fma.rn.f32x2 %0,%1,%2,%3;":"=l"(d):"l"(a),"l"(b),"l"(c)); return d; }
static __device__ __forceinline__ unsigned long long add2(unsigned long long a, unsigned long long b){
  unsigned long long d; asm("add.rn.f32x2 %0,%1,%2;":"=l"(d):"l"(a),"l"(b)); return d; }
static __device__ __forceinline__ float ex2f(float a){ float r; asm("ex2.approx.f32 %0,%1;":"=f"(r):"f"(a)); return r; }
static __device__ __forceinline__ float rcpf(float a){ float r; asm("rcp.approx.f32 %0,%1;":"=f"(r):"f"(a)); return r; }

// R3 structure (best: 380us) + software-pipelined x loads.
// 128-thread CTA = 2 independent warp-pairs (named barriers 1,2).
//   even warp: h = relu(x @ W1) -> smem (reduce-scatter, double buffered)
//   odd  warp: out = x * sigmoid(2*(h @ W2))  [-2*log2e folded into W2]
// Each role loads row r+1's x BEFORE computing row r, so the 234-262cyc
// L2 hit latency is covered by the ~280cyc compute block of the current row.
__global__ __launch_bounds__(128, 3) void fb_kernel(
    const float* __restrict__ x, const float* __restrict__ W1,
    const float* __restrict__ W2, float* __restrict__ out)
{
  __shared__ float hbuf[2][2][GSZ][16];   // [pair][buf][row][h]
  const int warp = threadIdx.x >> 5;
  const int lane = threadIdx.x & 31;
  const int pair = warp >> 1;
  const int role = warp & 1;
  const int vb = (int)blockIdx.x * 2 + pair;
  const int nstreams = (int)gridDim.x * 2;

  int myPhases = 0;
  if (vb < NPHASES) myPhases = (NPHASES - 1 - vb) / nstreams + 1;

  if (role == 0) {
    // W1 slice: input cols [lane*8,+8), all 16 outputs as 8 packed j-pairs.
    unsigned long long w1p[8][8];
    {
      const unsigned long long* w1u = (const unsigned long long*)W1;
      #pragma unroll
      for (int i = 0; i < 8; i++)
        #pragma unroll
        for (int p = 0; p < 8; p++)
          w1p[i][p] = __ldg(&w1u[(lane*8 + i)*8 + p]);
    }
    for (int it = 0; it <= myPhases; it++) {
      if (it < myPhases) {
        int phase = vb + it * nstreams;
        int base = phase * GSZ;
        int rows = min(GSZ, NROWS - base);
        float* hb = &hbuf[pair][it & 1][0][0];
        // preload row 0 of this phase
        const float4* xr0 = (const float4*)(x + (size_t)base * DIM) + lane*2;
        float4 a = __ldg(xr0), b = __ldg(xr0 + 1);
        #pragma unroll 1
        for (int r = 0; r < rows; r++) {
          // issue next row's loads FIRST (latency covered by compute below)
          int nr = r + 1; if (nr >= rows) nr = rows - 1;
          const float4* xrn = (const float4*)(x + (size_t)(base + nr) * DIM) + lane*2;
          float4 na = __ldg(xrn), nb = __ldg(xrn + 1);
          {
            int pr = base + r + 4; if (pr >= NROWS) pr = NROWS - 1;
            asm volatile("prefetch.global.L2 [%0];" :: "l"(x + (size_t)pr * DIM + lane*8));
          }
          float xs[8] = {a.x,a.y,a.z,a.w, b.x,b.y,b.z,b.w};
          unsigned long long acc[8];
          #pragma unroll
          for (int p=0;p<8;p++) acc[p] = 0ull;
          #pragma unroll
          for (int i=0;i<8;i++) {
            unsigned long long xi = pack2(xs[i], xs[i]);
            #pragma unroll
            for (int p=0;p<8;p++) acc[p] = fma2(xi, w1p[i][p], acc[p]);
          }
          // reduce-scatter: send the half I'm NOT keeping, keep my half.
          bool s16 = (lane & 16) != 0;
          bool s8  = (lane & 8)  != 0;
          bool s4  = (lane & 4)  != 0;
          #pragma unroll
          for (int p=0;p<4;p++) {
            unsigned long long send = s16 ? acc[p]   : acc[p+4];
            unsigned long long keep = s16 ? acc[p+4] : acc[p];
            acc[p] = add2(keep, __shfl_xor_sync(0xffffffffu, send, 16));
          }
          #pragma unroll
          for (int p=0;p<2;p++) {
            unsigned long long send = s8 ? acc[p]   : acc[p+2];
            unsigned long long keep = s8 ? acc[p+2] : acc[p];
            acc[p] = add2(keep, __shfl_xor_sync(0xffffffffu, send, 8));
          }
          {
            unsigned long long send = s4 ? acc[0] : acc[1];
            unsigned long long keep = s4 ? acc[1] : acc[0];
            acc[0] = add2(keep, __shfl_xor_sync(0xffffffffu, send, 4));
          }
          acc[0] = add2(acc[0], __shfl_xor_sync(0xffffffffu, acc[0], 2));
          acc[0] = add2(acc[0], __shfl_xor_sync(0xffffffffu, acc[0], 1));
          float h0, h1; unpack2(acc[0], h0, h1);
          h0 = fmaxf(h0, 0.f); h1 = fmaxf(h1, 0.f);
          if ((lane & 3) == 0) {
            int bix = ((lane>>2)&1)*2 + ((lane>>3)&1)*4 + ((lane>>4)&1)*8;
            *(float2*)(hb + r*16 + bix) = make_float2(h0, h1);
          }
          a = na; b = nb;
        }
      }
      asm volatile("bar.sync %0, 64;" :: "r"(1 + pair) : "memory");
    }
  } else {
    // W2 slice: output cols [lane*8,+8), all 16 inputs, pre-scaled by
    // -2*log2(e): sigmoid(2m) = rcp(1 + ex2(-2m*log2e)).
    unsigned long long w2p[16][4];
    {
      const float c = -2.0f * 1.4426950408889634f;
      #pragma unroll
      for (int j = 0; j < 16; j++)
        #pragma unroll
        for (int p = 0; p < 4; p++) {
          float a = __ldg(&W2[j*DIM + lane*8 + 2*p])     * c;
          float b = __ldg(&W2[j*DIM + lane*8 + 2*p + 1]) * c;
          w2p[j][p] = pack2(a, b);
        }
    }
    for (int it = 0; it <= myPhases; it++) {
      if (it >= 1) {
        int phase = vb + (it-1) * nstreams;
        int base = phase * GSZ;
        int rows = min(GSZ, NROWS - base);
        const float* hb = &hbuf[pair][(it-1) & 1][0][0];
        // preload row 0's gate x
        const float4* xr0 = (const float4*)(x + (size_t)base * DIM) + lane*2;
        float4 xa = __ldg(xr0), xb = __ldg(xr0 + 1);
        #pragma unroll 1
        for (int r = 0; r < rows; r++) {
          // next row's gate-x first (hidden behind fma+mufu block)
          int nr = r + 1; if (nr >= rows) nr = rows - 1;
          const float4* xrn = (const float4*)(x + (size_t)(base + nr) * DIM) + lane*2;
          float4 nxa = __ldg(xrn), nxb = __ldg(xrn + 1);
          unsigned long long acc[4];
          #pragma unroll
          for (int p=0;p<4;p++) acc[p] = 0ull;
          #pragma unroll
          for (int jj = 0; jj < 4; jj++) {
            float4 h4 = *(const float4*)(hb + r*16 + jj*4);  // broadcast LDS
            float hv[4] = {h4.x, h4.y, h4.z, h4.w};
            #pragma unroll
            for (int q = 0; q < 4; q++) {
              unsigned long long hj = pack2(hv[q], hv[q]);
              #pragma unroll
              for (int p=0;p<4;p++) acc[p] = fma2(hj, w2p[jj*4+q][p], acc[p]);
            }
          }
          float sg[8];
          #pragma unroll
          for (int p=0;p<4;p++) {
            float t0,t1; unpack2(acc[p], t0, t1);
            sg[2*p]   = rcpf(1.0f + ex2f(t0));
            sg[2*p+1] = rcpf(1.0f + ex2f(t1));
          }
          float4 o0 = make_float4(xa.x*sg[0], xa.y*sg[1], xa.z*sg[2], xa.w*sg[3]);
          float4 o1 = make_float4(xb.x*sg[4], xb.y*sg[5], xb.z*sg[6], xb.w*sg[7]);
          float4* orow = (float4*)(out + (size_t)(base + r) * DIM) + lane*2;
          orow[0] = o0; orow[1] = o1;
          xa = nxa; xb = nxb;
        }
      }
      asm volatile("bar.sync %0, 64;" :: "r"(1 + pair) : "memory");
    }
  }
}

extern "C" void kernel_launch(void* const* d_in, const int* in_sizes, int n_in,
                              void* d_out, int out_size) {
  const float* x  = (const float*)d_in[0];
  const float* W1 = (const float*)d_in[1];
  const float* W2 = (const float*)d_in[2];
  float* out = (float*)d_out;
  fb_kernel<<<444, 128>>>(x, W1, W2, out);
}